// round 17
// baseline (speedup 1.0000x reference)
#include <cuda_runtime.h>
#include <cstdint>
#include <cstddef>

#define NNODES 50000
#define NEDGES 1600000
#define HDIM   64
#define FNODE  8
#define FEDGE  8
#define NCLS   10

// ---------------- scratch (device globals; no allocation allowed) ----------
__device__ __align__(16) float g_h   [NNODES * HDIM];
__device__ __align__(16) float g_g   [NNODES * HDIM];
__device__ __align__(16) float g_dinv[NNODES];
__device__ __align__(16) float g_P   [NNODES * HDIM];
__device__ __align__(16) float g_Q   [NNODES * HDIM];
__device__ int  g_deg[NNODES];
__device__ int  g_off[NNODES + 1];
__device__ int  g_cur[NNODES];
__device__ int  g_csr[NEDGES];          // src indices grouped by dst

// ---------------- node encoder: h = x @ W_node + b_node --------------------
__global__ void __launch_bounds__(256) encoder_kernel(
    const float* __restrict__ x, const float* __restrict__ Wn,
    const float* __restrict__ bn)
{
    __shared__ float Ws[FNODE * HDIM];
    int tid = threadIdx.x;
    for (int i = tid; i < FNODE * HDIM; i += 256) Ws[i] = Wn[i];
    __syncthreads();
    int t = blockIdx.x * 256 + tid;
    int n = t >> 6, j = t & 63;
    float s = bn[j];
#pragma unroll
    for (int k = 0; k < FNODE; k++)
        s = fmaf(x[n * FNODE + k], Ws[k * HDIM + j], s);
    g_h[t] = s;
}

// ---------------- CSR build ------------------------------------------------
__global__ void zero_deg_kernel() {
    int n = blockIdx.x * 256 + threadIdx.x;
    if (n < NNODES) g_deg[n] = 0;
}
__global__ void hist_kernel(const int* __restrict__ dst) {
    int e = blockIdx.x * 256 + threadIdx.x;
    if (e < NEDGES) atomicAdd(&g_deg[dst[e]], 1);
}
__global__ void __launch_bounds__(1024) scan_kernel() {
    __shared__ int carry;
    __shared__ int warp_tot[32];
    int tid = threadIdx.x, lane = tid & 31, wid = tid >> 5;
    if (tid == 0) carry = 0;
    __syncthreads();
    for (int base = 0; base < NNODES; base += 1024) {
        int n = base + tid;
        int v = (n < NNODES) ? g_deg[n] : 0;
        int x = v;
#pragma unroll
        for (int o = 1; o < 32; o <<= 1) {
            int y = __shfl_up_sync(0xffffffffu, x, o);
            if (lane >= o) x += y;
        }
        if (lane == 31) warp_tot[wid] = x;
        __syncthreads();
        if (wid == 0) {
            int t = warp_tot[lane];
#pragma unroll
            for (int o = 1; o < 32; o <<= 1) {
                int y = __shfl_up_sync(0xffffffffu, t, o);
                if (lane >= o) t += y;
            }
            warp_tot[lane] = t;
        }
        __syncthreads();
        int incl = x + (wid > 0 ? warp_tot[wid - 1] : 0) + carry;
        if (n < NNODES) {
            int excl = incl - v;
            g_off[n] = excl;
            g_cur[n] = excl;
            g_dinv[n] = rsqrtf((float)(v + 1));   // +1 self-loop
        }
        __syncthreads();
        if (tid == 1023) carry = incl;
        __syncthreads();
    }
    if (tid == 0) g_off[NNODES] = NEDGES;
}
__global__ void fill_kernel(const int* __restrict__ src, const int* __restrict__ dst) {
    int e = blockIdx.x * 256 + threadIdx.x;
    if (e < NEDGES) {
        int pos = atomicAdd(&g_cur[dst[e]], 1);
        g_csr[pos] = src[e];
    }
}

// ------------- GCN transform: g = (h @ W) * dinv ---------------------------
__global__ void __launch_bounds__(256) gcn_transform_kernel(
    const float* __restrict__ W)
{
    __shared__ float Ws[HDIM * HDIM];
    __shared__ float hs[4 * HDIM];
    int tid = threadIdx.x;
#pragma unroll 4
    for (int i = tid; i < HDIM * HDIM; i += 256) Ws[i] = W[i];
    int n0 = blockIdx.x * 4;
    hs[tid] = g_h[n0 * HDIM + tid];
    __syncthreads();
    int nn = tid >> 6, j = tid & 63;
    float s = 0.f;
#pragma unroll
    for (int k = 0; k < HDIM; k++)
        s = fmaf(hs[nn * HDIM + k], Ws[k * HDIM + j], s);
    int n = n0 + nn;
    g_g[n * HDIM + j] = s * g_dinv[n];
}

// ------------- GCN gather+finish: warp per node, no atomics ----------------
__global__ void __launch_bounds__(256) gcn_gather_kernel(
    const float* __restrict__ b)
{
    int n = (blockIdx.x * 256 + threadIdx.x) >> 5;
    if (n >= NNODES) return;
    int lane = threadIdx.x & 31;
    int beg = g_off[n], end = g_off[n + 1];
    float a0 = g_g[(size_t)n * HDIM + lane];
    float a1 = g_g[(size_t)n * HDIM + 32 + lane];
    int j = beg;
    for (; j + 4 <= end; j += 4) {
        int s0 = g_csr[j], s1 = g_csr[j + 1], s2 = g_csr[j + 2], s3 = g_csr[j + 3];
        float v00 = g_g[(size_t)s0 * HDIM + lane];
        float v01 = g_g[(size_t)s0 * HDIM + 32 + lane];
        float v10 = g_g[(size_t)s1 * HDIM + lane];
        float v11 = g_g[(size_t)s1 * HDIM + 32 + lane];
        float v20 = g_g[(size_t)s2 * HDIM + lane];
        float v21 = g_g[(size_t)s2 * HDIM + 32 + lane];
        float v30 = g_g[(size_t)s3 * HDIM + lane];
        float v31 = g_g[(size_t)s3 * HDIM + 32 + lane];
        a0 += v00 + v10 + v20 + v30;
        a1 += v01 + v11 + v21 + v31;
    }
    for (; j < end; j++) {
        int s = g_csr[j];
        a0 += g_g[(size_t)s * HDIM + lane];
        a1 += g_g[(size_t)s * HDIM + 32 + lane];
    }
    float di = g_dinv[n];
    g_h[(size_t)n * HDIM + lane]      = fmaxf(fmaf(di, a0, b[lane]),      0.f);
    g_h[(size_t)n * HDIM + 32 + lane] = fmaxf(fmaf(di, a1, b[lane + 32]), 0.f);
}

// ------------- P = h@W1a + b1 ; Q = h@W1b ----------------------------------
__global__ void __launch_bounds__(256) pq_kernel(
    const float* __restrict__ W1, const float* __restrict__ b1)
{
    __shared__ float Ws[2 * HDIM * HDIM];
    __shared__ float hs[4 * HDIM];
    int tid = threadIdx.x;
#pragma unroll 8
    for (int i = tid; i < 2 * HDIM * HDIM; i += 256) Ws[i] = W1[i];
    int n0 = blockIdx.x * 4;
    hs[tid] = g_h[n0 * HDIM + tid];
    __syncthreads();
    int nn = tid >> 6, j = tid & 63;
    float p = b1[j], q = 0.f;
#pragma unroll
    for (int k = 0; k < HDIM; k++) {
        float hv = hs[nn * HDIM + k];
        p = fmaf(hv, Ws[k * HDIM + j], p);
        q = fmaf(hv, Ws[(HDIM + k) * HDIM + j], q);
    }
    int n = n0 + nn;
    g_P[n * HDIM + j] = p;
    g_Q[n * HDIM + j] = q;
}

// ===== edge MLP v7: double-buffered z1p, gather/compute software pipeline ==
// While phase 2 runs on buffer cur (tile t), the same threads issue tile
// t+1's P/Q/attr LDGs in 4 staggered single-edge chunks and build z1 into
// buffer nxt. Last chunk consumed after bar2 (ordered by next bar1).
#define TILE_E   64
#define TPH      10
#define SP1      68
#define SP2      36
#define OFF_W2D  0
#define OFF_W1C  16384
#define OFF_W3T  18432
#define OFF_B2   19712
#define OFF_B3   19840
#define OFF_HALF 19968
#define ZBUF_SZ  (HDIM * SP1 * 4)                 // 17408
#define HALF_SZ  (2 * ZBUF_SZ + TILE_E * SP2 * 4) // 44032
#define SMEM_V7  (OFF_HALF + 2 * HALF_SZ)         // 108032

__global__ void __launch_bounds__(256, 2) edge_mlp_v7_kernel(
    const int*   __restrict__ src, const int* __restrict__ dst,
    const float* __restrict__ ea,
    const float* __restrict__ W1,
    const float* __restrict__ W2,  const float* __restrict__ b2,
    const float* __restrict__ W3,  const float* __restrict__ b3,
    float*       __restrict__ out)
{
    extern __shared__ __align__(16) char sm[];
    float2* W2d  = (float2*)(sm + OFF_W2D);
    float*  W1cs = (float*)(sm + OFF_W1C);
    float*  W3ts = (float*)(sm + OFF_W3T);
    float*  b2s  = (float*)(sm + OFF_B2);
    float*  b3s  = (float*)(sm + OFF_B3);

    int tid = threadIdx.x;
    int h   = tid >> 7;
    int t128 = tid & 127;

    float* z1pA = (float*)(sm + OFF_HALF + h * HALF_SZ);
    float* z1pB = z1pA + HDIM * SP1;
    float* z2s  = z1pB + HDIM * SP1;

    // ---- stage weights once; W2d permuted: W2d[phys] = W2[logical] ----
    for (int i = tid; i < HDIM * 32; i += 256) {
        int kp = i >> 5, j = i & 31;
        int kl = (kp & 15) * 4 + (kp >> 4);
        float w = W2[kl * 32 + j];
        W2d[i] = make_float2(w, w);
    }
    for (int i = tid; i < FEDGE * HDIM; i += 256) W1cs[i] = W1[2 * HDIM * HDIM + i];
    for (int i = tid; i < NCLS * 32; i += 256) {
        int j = i >> 5, k = i & 31;
        W3ts[i] = W3[k * NCLS + j];
    }
    if (tid < 32)   b2s[tid] = b2[tid];
    if (tid < NCLS) b3s[tid] = b3[tid];
    __syncthreads();

    uint32_t zAb = (uint32_t)__cvta_generic_to_shared(z1pA);
    uint32_t zBb = (uint32_t)__cvta_generic_to_shared(z1pB);
    uint32_t w2b = (uint32_t)__cvta_generic_to_shared(W2d);

    int lane = t128 & 31, wrp = t128 >> 5;
    int sub = lane & 3;
    int jc  = lane >> 2;
    int j0  = jc * 4;
    int e2base = wrp * 16 + sub * 4;
    int el3 = t128 >> 1;
    int hf3 = t128 & 1;
    int bar = h + 1;
    int e_lo = wrp * 4 + (lane >> 3);    // phase-1 edge base (+ ep*16)
    int c0 = lane & 7, c1 = c0 + 8;      // chunk indices (float4 rows)

    const float4* W1c4 = (const float4*)W1cs;
    int tbase = blockIdx.x * (2 * TPH) + h * TPH;

    // per-(cell) z1 build: acc = P + Q + attr@W1c, relu, STS phys rows c+16r
#define Z1CELL(zn_, cc, Pv, Qv, av_)                                         \
    {                                                                        \
        float4 acc;                                                          \
        acc.x = Pv.x + Qv.x; acc.y = Pv.y + Qv.y;                            \
        acc.z = Pv.z + Qv.z; acc.w = Pv.w + Qv.w;                            \
        _Pragma("unroll")                                                    \
        for (int k8 = 0; k8 < 8; k8++) {                                     \
            float4 wv = W1c4[k8 * 16 + (cc)];                                \
            acc.x = fmaf(av_[k8], wv.x, acc.x);                              \
            acc.y = fmaf(av_[k8], wv.y, acc.y);                              \
            acc.z = fmaf(av_[k8], wv.z, acc.z);                              \
            acc.w = fmaf(av_[k8], wv.w, acc.w);                              \
        }                                                                    \
        float* zp = &(zn_)[(cc) * SP1 + ecur];                               \
        zp[0]        = fmaxf(acc.x, 0.f);                                    \
        zp[16 * SP1] = fmaxf(acc.y, 0.f);                                    \
        zp[32 * SP1] = fmaxf(acc.z, 0.f);                                    \
        zp[48 * SP1] = fmaxf(acc.w, 0.f);                                    \
    }

    // ---- prologue: build tile 0 into A (v6-style); prefetch idx tile 1 ----
    {
        int eb0 = tbase * TILE_E;
#pragma unroll
        for (int ep = 0; ep < 4; ep++) {
            int ecur = e_lo + ep * 16;
            int ge = eb0 + ecur;
            int s = src[ge], d = dst[ge];
            const float4* eap = (const float4*)(ea + (size_t)ge * FEDGE);
            float4 a0 = eap[0], a1 = eap[1];
            float av[8] = {a0.x, a0.y, a0.z, a0.w, a1.x, a1.y, a1.z, a1.w};
            float4 p0 = *((const float4*)(g_P + (size_t)s * HDIM) + c0);
            float4 q0 = *((const float4*)(g_Q + (size_t)d * HDIM) + c0);
            float4 p1 = *((const float4*)(g_P + (size_t)s * HDIM) + c1);
            float4 q1 = *((const float4*)(g_Q + (size_t)d * HDIM) + c1);
            Z1CELL(z1pA, c0, p0, q0, av);
            Z1CELL(z1pA, c1, p1, q1, av);
        }
    }
    int sA[4], dA[4];
    {
        int eb1 = (tbase + 1) * TILE_E;   // TPH>=2 always
#pragma unroll
        for (int ep = 0; ep < 4; ep++) {
            sA[ep] = src[eb1 + e_lo + ep * 16];
            dA[ep] = dst[eb1 + e_lo + ep * 16];
        }
    }

    float4 Pf0[2], Pf1[2], Qf0[2], Qf1[2], Af0[2], Af1[2];

#define ISSUE(ep)                                                            \
    {                                                                        \
        int sl = (ep) & 1;                                                   \
        int ge = ebn + e_lo + (ep) * 16;                                     \
        const float4* Pp = (const float4*)(g_P + (size_t)sA[ep] * HDIM);     \
        const float4* Qp = (const float4*)(g_Q + (size_t)dA[ep] * HDIM);     \
        Pf0[sl] = Pp[c0]; Pf1[sl] = Pp[c1];                                  \
        Qf0[sl] = Qp[c0]; Qf1[sl] = Qp[c1];                                  \
        const float4* eap = (const float4*)(ea + (size_t)ge * FEDGE);        \
        Af0[sl] = eap[0]; Af1[sl] = eap[1];                                  \
    }

#define CONSUME(ep, zn_)                                                     \
    {                                                                        \
        int sl = (ep) & 1;                                                   \
        int ecur = e_lo + (ep) * 16;                                         \
        float av[8] = {Af0[sl].x, Af0[sl].y, Af0[sl].z, Af0[sl].w,           \
                       Af1[sl].x, Af1[sl].y, Af1[sl].z, Af1[sl].w};          \
        Z1CELL(zn_, c0, Pf0[sl], Qf0[sl], av);                               \
        Z1CELL(zn_, c1, Pf1[sl], Qf1[sl], av);                               \
    }

#define P2CHUNK(K0)                                                          \
    _Pragma("unroll")                                                        \
    for (int k = (K0); k < (K0) + 16; k++) {                                 \
        uint64_t z01, z23, w0, w1, w2v, w3v;                                 \
        asm("ld.shared.v2.b64 {%0,%1}, [%2];"                                \
            : "=l"(z01), "=l"(z23) : "r"(za + k * (SP1 * 4)));               \
        asm("ld.shared.v2.b64 {%0,%1}, [%2];"                                \
            : "=l"(w0), "=l"(w1) : "r"(wa + k * 256));                       \
        asm("ld.shared.v2.b64 {%0,%1}, [%2];"                                \
            : "=l"(w2v), "=l"(w3v) : "r"(wa + k * 256 + 16));                \
        asm("fma.rn.f32x2 %0, %1, %2, %0;" : "+l"(acc01[0]) : "l"(z01), "l"(w0));   \
        asm("fma.rn.f32x2 %0, %1, %2, %0;" : "+l"(acc23[0]) : "l"(z23), "l"(w0));   \
        asm("fma.rn.f32x2 %0, %1, %2, %0;" : "+l"(acc01[1]) : "l"(z01), "l"(w1));   \
        asm("fma.rn.f32x2 %0, %1, %2, %0;" : "+l"(acc23[1]) : "l"(z23), "l"(w1));   \
        asm("fma.rn.f32x2 %0, %1, %2, %0;" : "+l"(acc01[2]) : "l"(z01), "l"(w2v));  \
        asm("fma.rn.f32x2 %0, %1, %2, %0;" : "+l"(acc23[2]) : "l"(z23), "l"(w2v));  \
        asm("fma.rn.f32x2 %0, %1, %2, %0;" : "+l"(acc01[3]) : "l"(z01), "l"(w3v));  \
        asm("fma.rn.f32x2 %0, %1, %2, %0;" : "+l"(acc23[3]) : "l"(z23), "l"(w3v));  \
    }

#pragma unroll 1
    for (int t = 0; t < TPH; ++t) {
        asm volatile("bar.sync %0, 128;" :: "r"(bar) : "memory");
        bool pf = (t + 1 < TPH);
        uint32_t zc = (t & 1) ? zBb : zAb;
        float*  zn = (t & 1) ? z1pA : z1pB;
        int ebase = (tbase + t) * TILE_E;
        int ebn   = (tbase + t + 1) * TILE_E;

        uint64_t acc01[4], acc23[4];
#pragma unroll
        for (int j = 0; j < 4; j++) {
            float bv = b2s[j0 + j];
            uint64_t bb;
            asm("mov.b64 %0, {%1, %1};" : "=l"(bb) : "f"(bv));
            acc01[j] = bb; acc23[j] = bb;
        }
        uint32_t za = zc + e2base * 4;
        uint32_t wa = w2b + j0 * 8;

        P2CHUNK(0)
        if (pf) ISSUE(0)
        P2CHUNK(16)
        if (pf) { ISSUE(1) CONSUME(0, zn) }
        P2CHUNK(32)
        if (pf) { ISSUE(2) CONSUME(1, zn) }
        P2CHUNK(48)
        if (pf) { ISSUE(3) CONSUME(2, zn) }

        // unpack z2, relu, store to z2s
        {
            float v0[4], v1[4], v2[4], v3[4];
#pragma unroll
            for (int j = 0; j < 4; j++) {
                float lo, hi;
                asm("mov.b64 {%0,%1}, %2;" : "=f"(lo), "=f"(hi) : "l"(acc01[j]));
                v0[j] = fmaxf(lo, 0.f); v1[j] = fmaxf(hi, 0.f);
                asm("mov.b64 {%0,%1}, %2;" : "=f"(lo), "=f"(hi) : "l"(acc23[j]));
                v2[j] = fmaxf(lo, 0.f); v3[j] = fmaxf(hi, 0.f);
            }
            *(float4*)&z2s[(e2base + 0) * SP2 + j0] = make_float4(v0[0], v0[1], v0[2], v0[3]);
            *(float4*)&z2s[(e2base + 1) * SP2 + j0] = make_float4(v1[0], v1[1], v1[2], v1[3]);
            *(float4*)&z2s[(e2base + 2) * SP2 + j0] = make_float4(v2[0], v2[1], v2[2], v2[3]);
            *(float4*)&z2s[(e2base + 3) * SP2 + j0] = make_float4(v3[0], v3[1], v3[2], v3[3]);
        }
        asm volatile("bar.sync %0, 128;" :: "r"(bar) : "memory");

        // consume last chunk (STS to zn ordered by NEXT bar1) + idx prefetch
        if (pf) {
            CONSUME(3, zn)
            if (t + 2 < TPH) {
                int eb2 = (tbase + t + 2) * TILE_E;
#pragma unroll
                for (int ep = 0; ep < 4; ep++) {
                    sA[ep] = src[eb2 + e_lo + ep * 16];
                    dA[ep] = dst[eb2 + e_lo + ep * 16];
                }
            }
        }

        // ---------------- Phase 3 ----------------
        {
            int jo = hf3 * 5;
            float acc[5];
#pragma unroll
            for (int j = 0; j < 5; j++) acc[j] = b3s[jo + j];
            const float4* z2v = (const float4*)&z2s[el3 * SP2];
#pragma unroll
            for (int k4 = 0; k4 < 8; k4++) {
                float4 z = z2v[k4];
#pragma unroll
                for (int j = 0; j < 5; j++) {
                    float4 w = *(const float4*)&W3ts[(jo + j) * 32 + k4 * 4];
                    acc[j] = fmaf(z.x, w.x, acc[j]);
                    acc[j] = fmaf(z.y, w.y, acc[j]);
                    acc[j] = fmaf(z.z, w.z, acc[j]);
                    acc[j] = fmaf(z.w, w.w, acc[j]);
                }
            }
            float* op = out + (size_t)(ebase + el3) * NCLS + jo;
#pragma unroll
            for (int j = 0; j < 5; j++) op[j] = acc[j];
        }
    }
}

// ---------------------------------------------------------------------------
extern "C" void kernel_launch(void* const* d_in, const int* in_sizes, int n_in,
                              void* d_out, int out_size)
{
    const float* x  = (const float*)d_in[0];
    const int*   ei = (const int*)  d_in[1];
    const float* ea = (const float*)d_in[2];
    const float* Wn = (const float*)d_in[3];
    const float* bn = (const float*)d_in[4];
    const float* Wc = (const float*)d_in[5];
    const float* bc = (const float*)d_in[6];
    const float* W1 = (const float*)d_in[7];
    const float* b1 = (const float*)d_in[8];
    const float* W2 = (const float*)d_in[9];
    const float* b2 = (const float*)d_in[10];
    const float* W3 = (const float*)d_in[11];
    const float* b3 = (const float*)d_in[12];
    const int* src = ei;
    const int* dst = ei + NEDGES;
    float* out = (float*)d_out;

    const int NH_BLKS = (NNODES * HDIM) / 256;
    const int N_BLKS  = (NNODES + 255) / 256;
    const int E_BLKS  = NEDGES / 256;
    const int W_BLKS  = (NNODES * 32 + 255) / 256;

    static bool attr_done = false;
    if (!attr_done) {
        cudaFuncSetAttribute(edge_mlp_v7_kernel,
                             cudaFuncAttributeMaxDynamicSharedMemorySize, SMEM_V7);
        attr_done = true;
    }

    // CSR build (also yields dinv)
    zero_deg_kernel<<<N_BLKS, 256>>>();
    hist_kernel<<<E_BLKS, 256>>>(dst);
    scan_kernel<<<1, 1024>>>();
    fill_kernel<<<E_BLKS, 256>>>(src, dst);

    // encoder
    encoder_kernel<<<NH_BLKS, 256>>>(x, Wn, bn);

    // 3 GCN layers
    for (int l = 0; l < 3; l++) {
        gcn_transform_kernel<<<NNODES / 4, 256>>>(Wc + l * HDIM * HDIM);
        gcn_gather_kernel<<<W_BLKS, 256>>>(bc + l * HDIM);
    }

    pq_kernel<<<NNODES / 4, 256>>>(W1, b1);

    // edge MLP v7: 1250 blocks x 256 thr, 20 tiles/block (10 per half)
    edge_mlp_v7_kernel<<<NEDGES / (TILE_E * 2 * TPH), 256, SMEM_V7>>>(
        src, dst, ea, W1, W2, b2, W3, b3, out);
}